// round 1
// baseline (speedup 1.0000x reference)
#include <cuda_runtime.h>

// Persistent-kernel STPN: f-state lives in registers across all 64 timesteps.
// 128 CTAs x 1024 threads (1 CTA/SM). CTA b handles h-rows {2*cta, 2*cta+1}
// for all 32 batches; warp = batch; lane l covers columns {4l+128k, k=0..3}.
// Grid-wide step synchronization via a CG-style phase barrier in global mem,
// with arrive/wait split so the f-update overlaps the barrier.

#define NCTA 128
#define NTHR 1024

namespace {
constexpr int kB = 32;
constexpr int kS = 64;
constexpr int kI = 256;
constexpr int kH = 256;
constexpr int kO = 128;
constexpr int kF = 512;  // kH + kI
}

__device__ unsigned g_count;               // barrier arrival counter (self-resetting)
__device__ unsigned g_phase;               // monotonically increasing barrier phase
__device__ float g_hbuf[3][kB * kH];       // triple-buffered hidden state

__device__ __forceinline__ unsigned ld_acq(unsigned* p) {
  unsigned v;
  asm volatile("ld.acquire.gpu.u32 %0, [%1];" : "=r"(v) : "l"(p) : "memory");
  return v;
}
__device__ __forceinline__ unsigned atom_add_acqrel(unsigned* p) {
  unsigned o;
  asm volatile("atom.add.acq_rel.gpu.u32 %0, [%1], 1;" : "=r"(o) : "l"(p) : "memory");
  return o;
}
__device__ __forceinline__ void st_rel(unsigned* p, unsigned v) {
  asm volatile("st.release.gpu.u32 [%0], %1;" :: "l"(p), "r"(v) : "memory");
}

__global__ void __launch_bounds__(NTHR, 1) stpn_kernel(
    const float* __restrict__ x,     // (B,S,I)
    const float* __restrict__ W,     // (H,F)
    const float* __restrict__ Lm,    // (H,F) weight_lambda
    const float* __restrict__ Gm,    // (H,F) weight_gamma
    const float* __restrict__ bias,  // (H)
    const float* __restrict__ ow,    // (O,H)
    const float* __restrict__ ob,    // (O)
    float* __restrict__ out)         // [tag (B,O) | h_fin (B,H) | f_fin (B,H,F)]
{
  __shared__ float sw[2][kF];
  __shared__ float sl[2][kF];
  __shared__ float sg[2][kF];

  const int tid  = threadIdx.x;
  const int lane = tid & 31;
  const int b    = tid >> 5;          // warp index = batch
  const int h0   = blockIdx.x * 2;    // first h-row of this CTA
  const int c0   = 4 * lane;          // base column of this lane

  // Load the CTA's weight rows into shared memory once (amortized over 64 steps).
  {
    float* pw = &sw[0][0];
    float* pl = &sl[0][0];
    float* pg = &sg[0][0];
    const int base = h0 * kF;
    for (int i = tid; i < 2 * kF; i += NTHR) {
      pw[i] = W[base + i];
      pl[i] = Lm[base + i];
      pg[i] = Gm[base + i];
    }
  }
  float biasr[2];
  biasr[0] = bias[h0];
  biasr[1] = bias[h0 + 1];

  unsigned phase0 = 0;
  if (tid == 0) phase0 = ld_acq(&g_phase);  // stable at launch start
  __syncthreads();

  // f-state in registers: f[row][k] covers cols c0+128k for this warp's batch.
  float4 f[2][4];
#pragma unroll
  for (int r = 0; r < 2; ++r)
#pragma unroll
    for (int k = 0; k < 4; ++k) f[r][k] = make_float4(0.f, 0.f, 0.f, 0.f);

  float hn[2] = {0.f, 0.f};

  for (int t = 0; t < kS; ++t) {
    const float* xrow = x + (b * kS + t) * kI;
    const int rb = (t + 2) % 3;   // read buffer (t-1)
    const int wb = t % 3;         // write buffer

    // ---------------- pass 1: pre = ti . (w+f), sq = |w+f|^2 ----------------
    float pre[2] = {0.f, 0.f};
    float sq[2]  = {0.f, 0.f};
#pragma unroll
    for (int k = 0; k < 4; ++k) {
      float4 ti;
      if (k < 2) {
        ti = *reinterpret_cast<const float4*>(xrow + c0 + 128 * k);
      } else if (t == 0) {
        ti = make_float4(0.f, 0.f, 0.f, 0.f);
      } else {
        ti = __ldcg(reinterpret_cast<const float4*>(
            &g_hbuf[rb][b * kH + c0 + 128 * (k - 2)]));
      }
#pragma unroll
      for (int r = 0; r < 2; ++r) {
        const float4 w4 = *reinterpret_cast<const float4*>(&sw[r][c0 + 128 * k]);
        float u;
        u = w4.x + f[r][k].x; pre[r] += ti.x * u; sq[r] += u * u;
        u = w4.y + f[r][k].y; pre[r] += ti.y * u; sq[r] += u * u;
        u = w4.z + f[r][k].z; pre[r] += ti.z * u; sq[r] += u * u;
        u = w4.w + f[r][k].w; pre[r] += ti.w * u; sq[r] += u * u;
      }
    }
    // Warp (= batch) reduction over all 512 columns.
#pragma unroll
    for (int off = 16; off; off >>= 1) {
      pre[0] += __shfl_xor_sync(0xffffffffu, pre[0], off);
      sq[0]  += __shfl_xor_sync(0xffffffffu, sq[0],  off);
      pre[1] += __shfl_xor_sync(0xffffffffu, pre[1], off);
      sq[1]  += __shfl_xor_sync(0xffffffffu, sq[1],  off);
    }
    float invn[2];
#pragma unroll
    for (int r = 0; r < 2; ++r) {
      invn[r] = 1.0f / (sqrtf(sq[r]) + 1e-16f);
      hn[r]   = tanhf(pre[r] * invn[r] + biasr[r]);
    }
    if (lane == 0) {
      g_hbuf[wb][b * kH + h0]     = hn[0];
      g_hbuf[wb][b * kH + h0 + 1] = hn[1];
    }
    __syncthreads();  // all h-writes of this CTA issued before arrive

    // ---------------- barrier arrive ----------------
    const unsigned target = phase0 + (unsigned)(t + 1);
    if (tid == 0) {
      unsigned old = atom_add_acqrel(&g_count);
      if (old == NCTA - 1) {
        g_count = 0;                 // ordered before release below
        st_rel(&g_phase, target);
      }
    }

    // ---------------- pass 2: f update (overlaps barrier latency) ----------
#pragma unroll
    for (int k = 0; k < 4; ++k) {
      float4 ti;
      if (k < 2) {
        ti = *reinterpret_cast<const float4*>(xrow + c0 + 128 * k);
      } else if (t == 0) {
        ti = make_float4(0.f, 0.f, 0.f, 0.f);
      } else {
        ti = __ldcg(reinterpret_cast<const float4*>(
            &g_hbuf[rb][b * kH + c0 + 128 * (k - 2)]));
      }
#pragma unroll
      for (int r = 0; r < 2; ++r) {
        const float4 l4 = *reinterpret_cast<const float4*>(&sl[r][c0 + 128 * k]);
        const float4 g4 = *reinterpret_cast<const float4*>(&sg[r][c0 + 128 * k]);
        const float iv = invn[r], hh = hn[r];
        f[r][k].x = fmaf(l4.x * iv, f[r][k].x, (g4.x * hh) * ti.x);
        f[r][k].y = fmaf(l4.y * iv, f[r][k].y, (g4.y * hh) * ti.y);
        f[r][k].z = fmaf(l4.z * iv, f[r][k].z, (g4.z * hh) * ti.z);
        f[r][k].w = fmaf(l4.w * iv, f[r][k].w, (g4.w * hh) * ti.w);
      }
    }

    // ---------------- barrier wait ----------------
    if (tid == 0) {
      while ((int)(ld_acq(&g_phase) - target) < 0) { }
    }
    __syncthreads();
  }

  // ---------------- epilogue ----------------
  // f_fin
  float* fout = out + kB * kO + kB * kH;
#pragma unroll
  for (int r = 0; r < 2; ++r) {
#pragma unroll
    for (int k = 0; k < 4; ++k) {
      *reinterpret_cast<float4*>(
          &fout[(size_t)(b * kH + h0 + r) * kF + c0 + 128 * k]) = f[r][k];
    }
  }
  // h_fin
  if (lane == 0) {
    out[kB * kO + b * kH + h0]     = hn[0];
    out[kB * kO + b * kH + h0 + 1] = hn[1];
  }

  // tag_space: CTA bb (< 32) computes row bb. 32 warps x 4 outputs each = 128.
  if (blockIdx.x < kB) {
    const int bb = blockIdx.x;
    const float* hf = &g_hbuf[(kS - 1) % 3][bb * kH];
#pragma unroll
    for (int j = 0; j < 4; ++j) {
      const int oo = (tid >> 5) * 4 + j;
      float p = 0.f;
#pragma unroll
      for (int m = 0; m < 8; ++m) {
        p += __ldcg(&hf[lane + 32 * m]) * ow[oo * kH + lane + 32 * m];
      }
#pragma unroll
      for (int off = 16; off; off >>= 1) p += __shfl_xor_sync(0xffffffffu, p, off);
      if (lane == 0) out[bb * kO + oo] = p + ob[oo];
    }
  }
}

extern "C" void kernel_launch(void* const* d_in, const int* in_sizes, int n_in,
                              void* d_out, int out_size) {
  (void)in_sizes; (void)n_in; (void)out_size;
  stpn_kernel<<<NCTA, NTHR>>>(
      (const float*)d_in[0],  // sentence
      (const float*)d_in[1],  // weight
      (const float*)d_in[2],  // weight_lambda
      (const float*)d_in[3],  // weight_gamma
      (const float*)d_in[4],  // bias
      (const float*)d_in[5],  // out_w
      (const float*)d_in[6],  // out_b
      (float*)d_out);
}